// round 9
// baseline (speedup 1.0000x reference)
#include <cuda_runtime.h>
#include <cstdint>

// Problem constants (fixed by the reference: B=8, S=1024, V=32000)
#define BB 8
#define SS 1024
#define VV 32000
#define NTHREADS 1024

// Output layout (float32, concatenated flattened tuple in return order):
//   [0,              8192)   draft        [B, S]
//   [8192,           8200)   num_newly    [B]
//   [8200,           8208)   num_acc      [B]
//   [8208,           264208) last_logits  [B, 1, V]
#define OFF_DRAFT   0
#define OFF_NEWLY   (BB * SS)
#define OFF_ACC     (BB * SS + BB)
#define OFF_LASTLOG (BB * SS + 2 * BB)

#define IDX_SENTINEL 0x7fffffff

// Monotone (for non-NaN) float -> uint32 key: preserves float ordering.
__device__ __forceinline__ unsigned int f2ord(float f) {
    unsigned int u = __float_as_uint(f);
    // negative floats: flip all bits; non-negative: set sign bit
    return u ^ ((unsigned int)((int)u >> 31) | 0x80000000u);
}

__global__ __launch_bounds__(NTHREADS, 1)
void eagle_verify_kernel(const int* __restrict__ input_ids,
                         const float* __restrict__ target_logits,
                         const int* __restrict__ npa_arr,
                         float* __restrict__ out) {
    const int b    = blockIdx.x;
    const int tid  = threadIdx.x;
    const int lane = tid & 31;
    const int warp = tid >> 5;

    const int*   ids = input_ids + b * SS;
    const float* lg  = target_logits + (size_t)b * SS * VV;
    float4* lastlog  = (float4*)(out + OFF_LASTLOG + (size_t)b * VV);

    __shared__ unsigned int s_val[32];
    __shared__ int          s_idx[32];

    const int npa = __ldg(&npa_arr[b]);

    // Hoisted epilogue load: retires under the chain's memory latency.
    const int my_shifted_id = (tid < SS - 1) ? __ldg(&ids[tid + 1]) : 0;

    int k = npa - 1;          // current logit row being checked
    int num_newly = 0;
    int bonus_tok = 0;
    bool first = true;        // block-uniform: skip the iter-0 reuse barrier

    const float NEG_INF = __int_as_float(0xff800000);

    // Sequential acceptance chain: argmax row k, compare with ids[k+1].
    // Expected ~1 iteration on random data; the final row's argmax is the
    // bonus token and the final row itself is last_logits (written fused,
    // speculatively, each iteration — later iterations overwrite).
    for (;;) {
        // protect s_val/s_idx reuse across iterations (not needed on iter 0;
        // `first` is uniform across the block so the barrier is legal)
        if (!first) __syncthreads();
        first = false;

        // prefetch the token we'll compare against (uniform per block)
        const int next_id = (k < SS - 1) ? __ldg(&ids[k + 1]) : -1;

        // ---- block-wide argmax of lg[k, :] + fused speculative row write ----
        // Full unroll (trip count is 7 or 8): ptxas front-batches all LDG.128s
        // -> MLP ~8, collapsing exposed DRAM latency to ~1 window per thread.
        const float4* row = (const float4*)(lg + (size_t)k * VV);
        float bestf = NEG_INF;
        int   bidx  = IDX_SENTINEL;

        #pragma unroll 8
        for (int i = tid; i < VV / 4; i += NTHREADS) {
            float4 v = __ldcs(&row[i]);   // streaming: touched once
            __stcs(&lastlog[i], v);       // speculative last_logits write
            int base = i << 2;
            // ascending index within thread -> strict '>' keeps first occurrence
            if (v.x > bestf) { bestf = v.x; bidx = base;     }
            if (v.y > bestf) { bestf = v.y; bidx = base + 1; }
            if (v.z > bestf) { bestf = v.z; bidx = base + 2; }
            if (v.w > bestf) { bestf = v.w; bidx = base + 3; }
        }

        // warp argmax via HW REDUX: max ordered value, then min index among
        // lanes holding that value (exact bitwise compare -> same semantics)
        unsigned int ordv = f2ord(bestf);
        unsigned int wmax = __reduce_max_sync(0xffffffffu, ordv);
        int widx = __reduce_min_sync(0xffffffffu,
                                     (ordv == wmax) ? bidx : IDX_SENTINEL);
        if (lane == 0) { s_val[warp] = wmax; s_idx[warp] = widx; }
        __syncthreads();

        // final reduce over the 32 warp partials, redundantly in every warp
        // (REDUX returns the result to all lanes -> no broadcast needed)
        unsigned int pv = s_val[lane];
        int          pi = s_idx[lane];
        unsigned int bmax = __reduce_max_sync(0xffffffffu, pv);
        const int greedy = __reduce_min_sync(0xffffffffu,
                                             (pv == bmax) ? pi : IDX_SENTINEL);

        // all threads evaluate the continuation condition identically
        if (greedy == next_id) {   // next_id == -1 at k == SS-1 never matches
            num_newly++;
            k++;
        } else {
            bonus_tok = greedy;
            break;
        }
    }

    const int num_acc = npa + num_newly;

    // ---- draft tokens: one element per thread (S == NTHREADS) ----
    {
        const int t = tid;
        float val;
        if (t < num_acc - 1)       val = (float)my_shifted_id;
        else if (t == num_acc - 1) val = (float)bonus_tok;
        else                       val = 0.0f;
        out[OFF_DRAFT + b * SS + t] = val;
    }

    // ---- scalars ----
    if (tid == 0) {
        out[OFF_NEWLY + b] = (float)num_newly;
        out[OFF_ACC   + b] = (float)num_acc;
    }
}

extern "C" void kernel_launch(void* const* d_in, const int* in_sizes, int n_in,
                              void* d_out, int out_size) {
    const int*   input_ids     = (const int*)d_in[0];
    const float* target_logits = (const float*)d_in[1];
    const int*   npa           = (const int*)d_in[2];
    float* out = (float*)d_out;

    eagle_verify_kernel<<<BB, NTHREADS>>>(input_ids, target_logits, npa, out);
}